// round 5
// baseline (speedup 1.0000x reference)
#include <cuda_runtime.h>
#include <math.h>

#define NTOK 49
#define DIM  96
#define QKVC 288

// ---- shared memory plan (floats) ----
// qs : [56][292]  q|k|v per token (rows 49..55 V-cols zeroed); later cols 0..95 reused for attn output
// xa : aliased region: x tile [49][100] (stages 0-1), then logits/probs [176][60] (stages 2-4)
constexpr int QS_STRIDE = 292;
constexpr int QS_ROWS   = 56;
constexpr int QS_SIZE   = QS_ROWS * QS_STRIDE;          // 16352
constexpr int AT_STRIDE = 60;                           // 60 mod 32 = 28 -> conflict-free frag loads
constexpr int AT_ROWS   = 3 * 56 + 8;                   // 176 (8 slack rows for padded m-tile reads)
constexpr int XA_SIZE   = AT_ROWS * AT_STRIDE;          // 10560 (also covers x tile reads up to row 63)
constexpr int XS_STRIDE = 100;
constexpr int SMEM_FLOATS = QS_SIZE + XA_SIZE;          // 26912
constexpr int SMEM_BYTES  = SMEM_FLOATS * 4;            // 107648 B -> 2 CTAs/SM

__device__ __forceinline__ unsigned f2tf(float f) {
    unsigned r;
    asm("cvt.rna.tf32.f32 %0, %1;" : "=r"(r) : "f"(f));
    return r;
}
__device__ __forceinline__ float tf32f(float f) { return __uint_as_float(f2tf(f)); }

__device__ __forceinline__ void mma_tf32(float& c0, float& c1, float& c2, float& c3,
                                         unsigned a0, unsigned a1, unsigned a2, unsigned a3,
                                         unsigned b0, unsigned b1) {
    asm volatile("mma.sync.aligned.m16n8k8.row.col.f32.tf32.tf32.f32 "
                 "{%0,%1,%2,%3}, {%4,%5,%6,%7}, {%8,%9}, {%0,%1,%2,%3};"
                 : "+f"(c0), "+f"(c1), "+f"(c2), "+f"(c3)
                 : "r"(a0), "r"(a1), "r"(a2), "r"(a3), "r"(b0), "r"(b1));
}

__global__ void __launch_bounds__(288, 2)
win_attn_kernel(const float* __restrict__ x,
                const float* __restrict__ qkv_w,
                const float* __restrict__ qkv_b,
                const float* __restrict__ proj_w,
                const float* __restrict__ proj_b,
                const float* __restrict__ bias_table,
                const int*   __restrict__ rel_index,
                float*       __restrict__ out)
{
    extern __shared__ float sm[];
    float* qs = sm;
    float* xa = sm + QS_SIZE;   // x tile, later attention logits/probs

    const int b    = blockIdx.x;
    const int tid  = threadIdx.x;
    const int warp = tid >> 5;            // 0..8
    const int lane = tid & 31;
    const int g    = lane >> 2;           // 0..7
    const int tg   = lane & 3;            // 0..3

    // ---- stage 0: load x (tf32-rounded) into xa; zero V pad rows ----
    const float* xg = x + (size_t)b * (NTOK * DIM);
    for (int i = tid; i < NTOK * DIM / 4; i += 288) {
        int n = i / (DIM / 4), k4 = i % (DIM / 4);
        float4 v = ((const float4*)xg)[i];
        float* d = &xa[n * XS_STRIDE + 4 * k4];
        d[0] = tf32f(v.x); d[1] = tf32f(v.y); d[2] = tf32f(v.z); d[3] = tf32f(v.w);
    }
    for (int i = tid; i < 7 * DIM; i += 288) {          // V rows 49..55 cols 192..287 = 0
        int r = 49 + i / DIM, c = 2 * DIM + i % DIM;
        qs[r * QS_STRIDE + c] = 0.f;
    }
    __syncthreads();

    // ---- stage 1: qkv = x @ qkv_w + qkv_b (tf32 mma). warp w owns cols [32w,32w+32) ----
    {
        const int ncol0 = warp * 32;
        const float sc = (warp < 3) ? 0.17677669529663687f : 1.0f;  // fold q-scale
        #pragma unroll 1
        for (int pass = 0; pass < 2; pass++) {
            const int m0 = pass * 32;                    // 2 m-tiles per pass
            float acc[2][4][4];
            #pragma unroll
            for (int mi = 0; mi < 2; mi++)
                #pragma unroll
                for (int ni = 0; ni < 4; ni++)
                    #pragma unroll
                    for (int j = 0; j < 4; j++) acc[mi][ni][j] = 0.f;

            #pragma unroll 1
            for (int k0 = 0; k0 < DIM; k0 += 8) {
                unsigned A[2][4];
                #pragma unroll
                for (int mi = 0; mi < 2; mi++) {
                    int r = m0 + mi * 16;
                    A[mi][0] = __float_as_uint(xa[(r + g)     * XS_STRIDE + k0 + tg]);
                    A[mi][1] = __float_as_uint(xa[(r + g + 8) * XS_STRIDE + k0 + tg]);
                    A[mi][2] = __float_as_uint(xa[(r + g)     * XS_STRIDE + k0 + tg + 4]);
                    A[mi][3] = __float_as_uint(xa[(r + g + 8) * XS_STRIDE + k0 + tg + 4]);
                }
                unsigned Bf[4][2];
                #pragma unroll
                for (int ni = 0; ni < 4; ni++) {
                    int c = ncol0 + ni * 8 + g;
                    Bf[ni][0] = f2tf(qkv_w[(k0 + tg)     * QKVC + c]);
                    Bf[ni][1] = f2tf(qkv_w[(k0 + tg + 4) * QKVC + c]);
                }
                #pragma unroll
                for (int mi = 0; mi < 2; mi++)
                    #pragma unroll
                    for (int ni = 0; ni < 4; ni++)
                        mma_tf32(acc[mi][ni][0], acc[mi][ni][1], acc[mi][ni][2], acc[mi][ni][3],
                                 A[mi][0], A[mi][1], A[mi][2], A[mi][3], Bf[ni][0], Bf[ni][1]);
            }
            #pragma unroll
            for (int mi = 0; mi < 2; mi++) {
                #pragma unroll
                for (int ni = 0; ni < 4; ni++) {
                    int c0 = ncol0 + ni * 8 + tg * 2;
                    float b0v = qkv_b[c0], b1v = qkv_b[c0 + 1];
                    int r = m0 + mi * 16 + g;
                    if (r < NTOK) {
                        qs[r * QS_STRIDE + c0]     = tf32f((acc[mi][ni][0] + b0v) * sc);
                        qs[r * QS_STRIDE + c0 + 1] = tf32f((acc[mi][ni][1] + b1v) * sc);
                    }
                    if (r + 8 < NTOK) {
                        qs[(r + 8) * QS_STRIDE + c0]     = tf32f((acc[mi][ni][2] + b0v) * sc);
                        qs[(r + 8) * QS_STRIDE + c0 + 1] = tf32f((acc[mi][ni][3] + b1v) * sc);
                    }
                }
            }
        }
    }
    __syncthreads();

    // ---- stage 2: logits = (q*scale) @ k^T + bias. 84 tiles (3 heads x 4 m x 7 n) ----
    {
        float* at = xa;
        #pragma unroll 1
        for (int t = warp; t < 84; t += 9) {
            int h = t / 28, rem = t % 28, mt = rem / 7, nt = rem % 7;
            int m0 = mt * 16, n0 = nt * 8;
            float c0 = 0.f, c1 = 0.f, c2 = 0.f, c3 = 0.f;
            #pragma unroll
            for (int k0 = 0; k0 < 32; k0 += 8) {
                int qc = h * 32 + k0;
                unsigned a0 = __float_as_uint(qs[(m0 + g)     * QS_STRIDE + qc + tg]);
                unsigned a1 = __float_as_uint(qs[(m0 + g + 8) * QS_STRIDE + qc + tg]);
                unsigned a2 = __float_as_uint(qs[(m0 + g)     * QS_STRIDE + qc + tg + 4]);
                unsigned a3 = __float_as_uint(qs[(m0 + g + 8) * QS_STRIDE + qc + tg + 4]);
                unsigned b0 = __float_as_uint(qs[(n0 + g) * QS_STRIDE + DIM + qc + tg]);
                unsigned b1 = __float_as_uint(qs[(n0 + g) * QS_STRIDE + DIM + qc + tg + 4]);
                mma_tf32(c0, c1, c2, c3, a0, a1, a2, a3, b0, b1);
            }
            int n_0 = n0 + tg * 2;
            #pragma unroll
            for (int e = 0; e < 4; e++) {
                int m = m0 + g + ((e >> 1) ? 8 : 0);
                int n = n_0 + (e & 1);
                float v = (e == 0) ? c0 : (e == 1) ? c1 : (e == 2) ? c2 : c3;
                if (m < NTOK && n < NTOK)
                    at[(h * 56 + m) * AT_STRIDE + n] =
                        v + bias_table[rel_index[m * NTOK + n] * 3 + h];
            }
        }
    }
    __syncthreads();

    // ---- stage 3: softmax per row; write rounded probs, zero pad cols 49..55 ----
    {
        float* at = xa;
        #pragma unroll 1
        for (int r = warp; r < 3 * NTOK; r += 9) {
            int h = r / NTOK, m = r % NTOK;
            float* row = &at[(h * 56 + m) * AT_STRIDE];
            float v0 = row[lane];
            float v1 = (lane < 17) ? row[lane + 32] : -INFINITY;
            float mx = fmaxf(v0, v1);
            #pragma unroll
            for (int o = 16; o > 0; o >>= 1) mx = fmaxf(mx, __shfl_xor_sync(0xffffffffu, mx, o));
            float e0 = __expf(v0 - mx);
            float e1 = (lane < 17) ? __expf(v1 - mx) : 0.f;
            float s = e0 + e1;
            #pragma unroll
            for (int o = 16; o > 0; o >>= 1) s += __shfl_xor_sync(0xffffffffu, s, o);
            float inv = 1.0f / s;
            row[lane] = tf32f(e0 * inv);
            if (lane < 17) row[lane + 32] = tf32f(e1 * inv);
            if (lane >= 25) row[lane + 24] = 0.f;   // cols 49..55 := 0 (contraction pad)
        }
    }
    __syncthreads();

    // ---- stage 4: O = P @ V -> qs cols 0..95. 48 tiles (3 heads x 4 m x 4 n), K padded to 56 ----
    {
        float* at = xa;
        #pragma unroll 1
        for (int t = warp; t < 48; t += 9) {
            int h = t / 16, rem = t % 16, mt = rem / 4, nt = rem % 4;
            int m0 = mt * 16, n0 = nt * 8;
            float c0 = 0.f, c1 = 0.f, c2 = 0.f, c3 = 0.f;
            #pragma unroll
            for (int k0 = 0; k0 < 56; k0 += 8) {
                unsigned a0 = __float_as_uint(at[(h * 56 + m0 + g)     * AT_STRIDE + k0 + tg]);
                unsigned a1 = __float_as_uint(at[(h * 56 + m0 + g + 8) * AT_STRIDE + k0 + tg]);
                unsigned a2 = __float_as_uint(at[(h * 56 + m0 + g)     * AT_STRIDE + k0 + tg + 4]);
                unsigned a3 = __float_as_uint(at[(h * 56 + m0 + g + 8) * AT_STRIDE + k0 + tg + 4]);
                int vc = 2 * DIM + h * 32 + n0 + g;
                unsigned b0 = __float_as_uint(qs[(k0 + tg)     * QS_STRIDE + vc]);
                unsigned b1 = __float_as_uint(qs[(k0 + tg + 4) * QS_STRIDE + vc]);
                mma_tf32(c0, c1, c2, c3, a0, a1, a2, a3, b0, b1);
            }
            int c_0 = h * 32 + n0 + tg * 2;
            int m = m0 + g;
            if (m < NTOK) {
                qs[m * QS_STRIDE + c_0]     = tf32f(c0);
                qs[m * QS_STRIDE + c_0 + 1] = tf32f(c1);
            }
            if (m + 8 < NTOK) {
                qs[(m + 8) * QS_STRIDE + c_0]     = tf32f(c2);
                qs[(m + 8) * QS_STRIDE + c_0 + 1] = tf32f(c3);
            }
        }
    }
    __syncthreads();

    // ---- stage 5: out = O @ proj_w + proj_b. 48 tiles (4 m x 12 n), K=96 ----
    {
        float* og = out + (size_t)b * (NTOK * DIM);
        #pragma unroll 1
        for (int t = warp; t < 48; t += 9) {
            int mt = t / 12, nt = t % 12;
            int m0 = mt * 16, n0 = nt * 8;
            float c0 = 0.f, c1 = 0.f, c2 = 0.f, c3 = 0.f;
            #pragma unroll
            for (int k0 = 0; k0 < DIM; k0 += 8) {
                unsigned a0 = __float_as_uint(qs[(m0 + g)     * QS_STRIDE + k0 + tg]);
                unsigned a1 = __float_as_uint(qs[(m0 + g + 8) * QS_STRIDE + k0 + tg]);
                unsigned a2 = __float_as_uint(qs[(m0 + g)     * QS_STRIDE + k0 + tg + 4]);
                unsigned a3 = __float_as_uint(qs[(m0 + g + 8) * QS_STRIDE + k0 + tg + 4]);
                unsigned b0 = f2tf(proj_w[(k0 + tg)     * DIM + n0 + g]);
                unsigned b1 = f2tf(proj_w[(k0 + tg + 4) * DIM + n0 + g]);
                mma_tf32(c0, c1, c2, c3, a0, a1, a2, a3, b0, b1);
            }
            int n_0 = n0 + tg * 2;
            float pb0 = proj_b[n_0], pb1 = proj_b[n_0 + 1];
            int m = m0 + g;
            if (m < NTOK) {
                og[m * DIM + n_0]     = c0 + pb0;
                og[m * DIM + n_0 + 1] = c1 + pb1;
            }
            if (m + 8 < NTOK) {
                og[(m + 8) * DIM + n_0]     = c2 + pb0;
                og[(m + 8) * DIM + n_0 + 1] = c3 + pb1;
            }
        }
    }
}

extern "C" void kernel_launch(void* const* d_in, const int* in_sizes, int n_in,
                              void* d_out, int out_size)
{
    const float* x          = (const float*)d_in[0];
    // d_in[1] = q_global (unused by forward)
    const float* qkv_w      = (const float*)d_in[2];
    const float* qkv_b      = (const float*)d_in[3];
    const float* proj_w     = (const float*)d_in[4];
    const float* proj_b     = (const float*)d_in[5];
    const float* bias_table = (const float*)d_in[6];
    const int*   rel_index  = (const int*)d_in[7];
    float* out = (float*)d_out;

    int nwin = in_sizes[0] / (NTOK * DIM);

    cudaFuncSetAttribute(win_attn_kernel,
                         cudaFuncAttributeMaxDynamicSharedMemorySize, SMEM_BYTES);
    win_attn_kernel<<<nwin, 288, SMEM_BYTES>>>(x, qkv_w, qkv_b, proj_w, proj_b,
                                               bias_table, rel_index, out);
    (void)n_in; (void)out_size;
}

// round 6
// speedup vs baseline: 2.3030x; 2.3030x over previous
#include <cuda_runtime.h>
#include <math.h>

#define NTOK 49
#define DIM  96
#define QKVC 288

// ---- shared memory plan (floats) ----
constexpr int QS_STRIDE = 196;                 // q|k rows (56), cols 0..95 Q->O, 96..191 K
constexpr int QS_SIZE   = 56 * QS_STRIDE;      // 10976
constexpr int AT_STRIDE = 60;                  // probs P [3*56+8][60]; also x tile [49][100]
constexpr int AT_ROWS   = 176;
constexpr int XA_SIZE   = AT_ROWS * AT_STRIDE; // 10560
constexpr int VT_STRIDE = 60;                  // V transposed [96][60] (cols=token, padded)
constexpr int VT_SIZE   = 96 * VT_STRIDE;      // 5760
constexpr int XS_STRIDE = 100;
constexpr int SMEM_FLOATS = QS_SIZE + XA_SIZE + VT_SIZE;   // 27296
constexpr int SMEM_BYTES  = SMEM_FLOATS * 4;               // 109184 -> 2 CTAs/SM

// ---- precomputed weights (tf32, fragment-paired) + fused bias ----
__device__ float2 g_wq[12 * QKVC * 4];   // [kk][c][tg] = {W[8kk+tg][c], W[8kk+tg+4][c]}
__device__ float2 g_wp[12 * DIM * 4];
__device__ float  g_bias[3 * 64 * 56];   // [h][m][n] fused bias_table[rel_index]

__device__ __forceinline__ unsigned f2tf(float f) {
    unsigned r; asm("cvt.rna.tf32.f32 %0, %1;" : "=r"(r) : "f"(f)); return r;
}
__device__ __forceinline__ float tf32f(float f) { return __uint_as_float(f2tf(f)); }

__device__ __forceinline__ void mma_tf32(float& c0, float& c1, float& c2, float& c3,
                                         unsigned a0, unsigned a1, unsigned a2, unsigned a3,
                                         unsigned b0, unsigned b1) {
    asm volatile("mma.sync.aligned.m16n8k8.row.col.f32.tf32.tf32.f32 "
                 "{%0,%1,%2,%3}, {%4,%5,%6,%7}, {%8,%9}, {%0,%1,%2,%3};"
                 : "+f"(c0), "+f"(c1), "+f"(c2), "+f"(c3)
                 : "r"(a0), "r"(a1), "r"(a2), "r"(a3), "r"(b0), "r"(b1));
}
__device__ __forceinline__ void ldsm_x4(unsigned& a0, unsigned& a1, unsigned& a2, unsigned& a3,
                                        unsigned addr) {
    asm volatile("ldmatrix.sync.aligned.m8n8.x4.shared.b16 {%0,%1,%2,%3}, [%4];"
                 : "=r"(a0), "=r"(a1), "=r"(a2), "=r"(a3) : "r"(addr));
}
__device__ __forceinline__ void ldsm_x2(unsigned& b0, unsigned& b1, unsigned addr) {
    asm volatile("ldmatrix.sync.aligned.m8n8.x2.shared.b16 {%0,%1}, [%2];"
                 : "=r"(b0), "=r"(b1) : "r"(addr));
}
__device__ __forceinline__ unsigned s2u(const void* p) {
    return (unsigned)__cvta_generic_to_shared(p);
}

__global__ void prep_kernel(const float* __restrict__ qkv_w, const float* __restrict__ proj_w,
                            const float* __restrict__ bias_table, const int* __restrict__ rel_index) {
    int i = blockIdx.x * 256 + threadIdx.x;
    if (i < 12 * QKVC * 4) {
        int kk = i / (QKVC * 4), rem = i % (QKVC * 4), c = rem >> 2, tg = rem & 3;
        g_wq[i] = make_float2(__uint_as_float(f2tf(qkv_w[(kk * 8 + tg) * QKVC + c])),
                              __uint_as_float(f2tf(qkv_w[(kk * 8 + tg + 4) * QKVC + c])));
    }
    if (i < 12 * DIM * 4) {
        int kk = i / (DIM * 4), rem = i % (DIM * 4), c = rem >> 2, tg = rem & 3;
        g_wp[i] = make_float2(__uint_as_float(f2tf(proj_w[(kk * 8 + tg) * DIM + c])),
                              __uint_as_float(f2tf(proj_w[(kk * 8 + tg + 4) * DIM + c])));
    }
    if (i < 3 * 64 * 56) {
        int h = i / (64 * 56), rem = i % (64 * 56), m = rem / 56, n = rem % 56;
        g_bias[i] = (m < NTOK && n < NTOK) ? bias_table[rel_index[m * NTOK + n] * 3 + h] : 0.f;
    }
}

__global__ void __launch_bounds__(288, 2)
win_attn_kernel(const float* __restrict__ x,
                const float* __restrict__ qkv_b,
                const float* __restrict__ proj_b,
                float*       __restrict__ out)
{
    extern __shared__ float sm[];
    float* qs = sm;                 // [56][196]
    float* xa = sm + QS_SIZE;       // x tile [49][100] then P [176][60]
    float* vt = xa + XA_SIZE;       // V^T [96][60]

    const int b    = blockIdx.x;
    const int tid  = threadIdx.x;
    const int warp = tid >> 5;
    const int lane = tid & 31;
    const int g    = lane >> 2;
    const int tg   = lane & 3;
    const int rl   = lane & 7;
    const int sel  = lane >> 3;          // x4 matrix select
    const int sel2 = (lane >> 3) & 1;    // x2 matrix select
    const float NEGINF = __int_as_float(0xff800000);

    const unsigned qs_u = s2u(qs);
    const unsigned xa_u = s2u(xa);
    const unsigned vt_u = s2u(vt);

    // ---- stage 0: load x (tf32-rounded) -> xa; zero V^T token pad cols ----
    const float* xg = x + (size_t)b * (NTOK * DIM);
    for (int i = tid; i < NTOK * DIM / 4; i += 288) {
        int n = i / (DIM / 4), k4 = i % (DIM / 4);
        float4 v = ((const float4*)xg)[i];
        float* d = &xa[n * XS_STRIDE + 4 * k4];
        d[0] = tf32f(v.x); d[1] = tf32f(v.y); d[2] = tf32f(v.z); d[3] = tf32f(v.w);
    }
    for (int i = tid; i < 96 * 11; i += 288) {
        int r = i / 11, c = 49 + i % 11;
        vt[r * VT_STRIDE + c] = 0.f;
    }
    __syncthreads();

    // ---- stage 1: qkv = x @ Wqkv + b. warp w -> 32 cols; 4 m-tiles, 4 n-tiles ----
    {
        const int c0w = warp * 32;
        const float sc = (warp < 3) ? 0.17677669529663687f : 1.0f;

        unsigned aaddr[4];
        #pragma unroll
        for (int mt = 0; mt < 4; mt++)
            aaddr[mt] = xa_u + (((mt * 16 + rl + ((sel & 1) << 3)) * XS_STRIDE
                                 + ((sel >> 1) << 2)) << 2);

        float acc[4][4][4];
        #pragma unroll
        for (int mt = 0; mt < 4; mt++)
            #pragma unroll
            for (int ni = 0; ni < 4; ni++)
                #pragma unroll
                for (int j = 0; j < 4; j++) acc[mt][ni][j] = 0.f;

        float2 Bc[4];
        #pragma unroll
        for (int ni = 0; ni < 4; ni++)
            Bc[ni] = g_wq[(c0w + ni * 8 + g) * 4 + tg];

        #pragma unroll 1
        for (int kk = 0; kk < 12; kk++) {
            unsigned A[4][4];
            #pragma unroll
            for (int mt = 0; mt < 4; mt++) {
                ldsm_x4(A[mt][0], A[mt][1], A[mt][2], A[mt][3], aaddr[mt]);
                aaddr[mt] += 32;
            }
            float2 Bn[4];
            if (kk < 11) {
                #pragma unroll
                for (int ni = 0; ni < 4; ni++)
                    Bn[ni] = g_wq[((kk + 1) * QKVC + c0w + ni * 8 + g) * 4 + tg];
            }
            #pragma unroll
            for (int mt = 0; mt < 4; mt++)
                #pragma unroll
                for (int ni = 0; ni < 4; ni++)
                    mma_tf32(acc[mt][ni][0], acc[mt][ni][1], acc[mt][ni][2], acc[mt][ni][3],
                             A[mt][0], A[mt][1], A[mt][2], A[mt][3],
                             __float_as_uint(Bc[ni].x), __float_as_uint(Bc[ni].y));
            #pragma unroll
            for (int ni = 0; ni < 4; ni++) Bc[ni] = Bn[ni];
        }

        float2 qb[4];
        #pragma unroll
        for (int ni = 0; ni < 4; ni++)
            qb[ni] = *(const float2*)&qkv_b[c0w + ni * 8 + tg * 2];

        #pragma unroll
        for (int mt = 0; mt < 4; mt++) {
            int rA = mt * 16 + g, rB = rA + 8;
            #pragma unroll
            for (int ni = 0; ni < 4; ni++) {
                float v0 = tf32f((acc[mt][ni][0] + qb[ni].x) * sc);
                float v1 = tf32f((acc[mt][ni][1] + qb[ni].y) * sc);
                float v2 = tf32f((acc[mt][ni][2] + qb[ni].x) * sc);
                float v3 = tf32f((acc[mt][ni][3] + qb[ni].y) * sc);
                if (warp < 6) {
                    int col = ((warp < 3) ? warp * 32 : 96 + (warp - 3) * 32) + ni * 8 + tg * 2;
                    if (rA < NTOK) *(float2*)&qs[rA * QS_STRIDE + col] = make_float2(v0, v1);
                    if (rB < NTOK) *(float2*)&qs[rB * QS_STRIDE + col] = make_float2(v2, v3);
                } else {
                    int vc = (warp - 6) * 32 + ni * 8 + tg * 2;
                    if (rA < NTOK) { vt[vc * VT_STRIDE + rA] = v0; vt[(vc + 1) * VT_STRIDE + rA] = v1; }
                    if (rB < NTOK) { vt[vc * VT_STRIDE + rB] = v2; vt[(vc + 1) * VT_STRIDE + rB] = v3; }
                }
            }
        }
    }
    __syncthreads();

    // ---- stages 2-4 fused: per job (h, m-tile): logits -> softmax (regs) -> P -> P@V -> O ----
    #pragma unroll 1
    for (int t = warp; t < 12; t += 9) {
        const int h = t >> 2, mt = t & 3, m0 = mt * 16;
        const int rA = m0 + g, rB = rA + 8;

        // logits = Qs @ K^T
        float a[7][4];
        #pragma unroll
        for (int nt = 0; nt < 7; nt++)
            #pragma unroll
            for (int j = 0; j < 4; j++) a[nt][j] = 0.f;

        unsigned qaddr = qs_u + (((m0 + rl + ((sel & 1) << 3)) * QS_STRIDE
                                  + h * 32 + ((sel >> 1) << 2)) << 2);
        unsigned kaddr[7];
        #pragma unroll
        for (int nt = 0; nt < 7; nt++)
            kaddr[nt] = qs_u + (((nt * 8 + rl) * QS_STRIDE + 96 + h * 32 + (sel2 << 2)) << 2);

        #pragma unroll
        for (int ks = 0; ks < 4; ks++) {
            unsigned A0, A1, A2, A3;
            ldsm_x4(A0, A1, A2, A3, qaddr); qaddr += 32;
            #pragma unroll
            for (int nt = 0; nt < 7; nt++) {
                unsigned b0, b1;
                ldsm_x2(b0, b1, kaddr[nt]); kaddr[nt] += 32;
                mma_tf32(a[nt][0], a[nt][1], a[nt][2], a[nt][3], A0, A1, A2, A3, b0, b1);
            }
        }

        // + fused bias, -inf mask on pad cols
        #pragma unroll
        for (int nt = 0; nt < 7; nt++) {
            int n0p = nt * 8 + tg * 2;
            float2 bA = *(const float2*)&g_bias[(h * 64 + rA) * 56 + n0p];
            float2 bB = *(const float2*)&g_bias[(h * 64 + rB) * 56 + n0p];
            a[nt][0] = (n0p     < NTOK) ? a[nt][0] + bA.x : NEGINF;
            a[nt][1] = (n0p + 1 < NTOK) ? a[nt][1] + bA.y : NEGINF;
            a[nt][2] = (n0p     < NTOK) ? a[nt][2] + bB.x : NEGINF;
            a[nt][3] = (n0p + 1 < NTOK) ? a[nt][3] + bB.y : NEGINF;
        }

        // register softmax (rows rA and rB live in the 4-lane quad with same g)
        float mA = NEGINF, mB = NEGINF;
        #pragma unroll
        for (int nt = 0; nt < 7; nt++) {
            mA = fmaxf(mA, fmaxf(a[nt][0], a[nt][1]));
            mB = fmaxf(mB, fmaxf(a[nt][2], a[nt][3]));
        }
        mA = fmaxf(mA, __shfl_xor_sync(0xffffffffu, mA, 1));
        mA = fmaxf(mA, __shfl_xor_sync(0xffffffffu, mA, 2));
        mB = fmaxf(mB, __shfl_xor_sync(0xffffffffu, mB, 1));
        mB = fmaxf(mB, __shfl_xor_sync(0xffffffffu, mB, 2));
        float sA = 0.f, sB = 0.f;
        #pragma unroll
        for (int nt = 0; nt < 7; nt++) {
            a[nt][0] = __expf(a[nt][0] - mA);
            a[nt][1] = __expf(a[nt][1] - mA);
            a[nt][2] = __expf(a[nt][2] - mB);
            a[nt][3] = __expf(a[nt][3] - mB);
            sA += a[nt][0] + a[nt][1];
            sB += a[nt][2] + a[nt][3];
        }
        sA += __shfl_xor_sync(0xffffffffu, sA, 1);
        sA += __shfl_xor_sync(0xffffffffu, sA, 2);
        sB += __shfl_xor_sync(0xffffffffu, sB, 1);
        sB += __shfl_xor_sync(0xffffffffu, sB, 2);
        float iA = 1.0f / sA, iB = 1.0f / sB;

        // store P (tf32) for ldmatrix consumption; pad cols are exact 0
        #pragma unroll
        for (int nt = 0; nt < 7; nt++) {
            int n0p = nt * 8 + tg * 2;
            if (rA < NTOK)
                *(float2*)&xa[(h * 56 + rA) * AT_STRIDE + n0p] =
                    make_float2(tf32f(a[nt][0] * iA), tf32f(a[nt][1] * iA));
            if (rB < NTOK)
                *(float2*)&xa[(h * 56 + rB) * AT_STRIDE + n0p] =
                    make_float2(tf32f(a[nt][2] * iB), tf32f(a[nt][3] * iB));
        }
        __syncwarp();

        // O = P @ V^T  (K padded to 56, pad cols of P are zero)
        float o[4][4];
        #pragma unroll
        for (int nt = 0; nt < 4; nt++)
            #pragma unroll
            for (int j = 0; j < 4; j++) o[nt][j] = 0.f;

        unsigned paddr = xa_u + (((h * 56 + m0 + rl + ((sel & 1) << 3)) * AT_STRIDE
                                  + ((sel >> 1) << 2)) << 2);
        unsigned vaddr[4];
        #pragma unroll
        for (int nt = 0; nt < 4; nt++)
            vaddr[nt] = vt_u + (((h * 32 + nt * 8 + rl) * VT_STRIDE + (sel2 << 2)) << 2);

        #pragma unroll
        for (int ks = 0; ks < 7; ks++) {
            unsigned A0, A1, A2, A3;
            ldsm_x4(A0, A1, A2, A3, paddr); paddr += 32;
            #pragma unroll
            for (int nt = 0; nt < 4; nt++) {
                unsigned b0, b1;
                ldsm_x2(b0, b1, vaddr[nt]); vaddr[nt] += 32;
                mma_tf32(o[nt][0], o[nt][1], o[nt][2], o[nt][3], A0, A1, A2, A3, b0, b1);
            }
        }
        #pragma unroll
        for (int nt = 0; nt < 4; nt++) {
            int col = h * 32 + nt * 8 + tg * 2;
            if (rA < NTOK) *(float2*)&qs[rA * QS_STRIDE + col] =
                make_float2(tf32f(o[nt][0]), tf32f(o[nt][1]));
            if (rB < NTOK) *(float2*)&qs[rB * QS_STRIDE + col] =
                make_float2(tf32f(o[nt][2]), tf32f(o[nt][3]));
        }
    }
    __syncthreads();

    // ---- stage 5: out = O @ Wproj + b. 8 jobs: (m-tile, col-half of 48) ----
    if (warp < 8) {
        const int mt = warp >> 1, nh = warp & 1;
        const int m0 = mt * 16, nc0 = nh * 48;
        const int rA = m0 + g, rB = rA + 8;

        float acc[6][4];
        #pragma unroll
        for (int ni = 0; ni < 6; ni++)
            #pragma unroll
            for (int j = 0; j < 4; j++) acc[ni][j] = 0.f;

        unsigned aaddr = qs_u + (((m0 + rl + ((sel & 1) << 3)) * QS_STRIDE
                                  + ((sel >> 1) << 2)) << 2);
        float2 Bc[6];
        #pragma unroll
        for (int ni = 0; ni < 6; ni++)
            Bc[ni] = g_wp[(nc0 + ni * 8 + g) * 4 + tg];

        #pragma unroll 1
        for (int kk = 0; kk < 12; kk++) {
            unsigned A0, A1, A2, A3;
            ldsm_x4(A0, A1, A2, A3, aaddr); aaddr += 32;
            float2 Bn[6];
            if (kk < 11) {
                #pragma unroll
                for (int ni = 0; ni < 6; ni++)
                    Bn[ni] = g_wp[((kk + 1) * DIM + nc0 + ni * 8 + g) * 4 + tg];
            }
            #pragma unroll
            for (int ni = 0; ni < 6; ni++)
                mma_tf32(acc[ni][0], acc[ni][1], acc[ni][2], acc[ni][3],
                         A0, A1, A2, A3,
                         __float_as_uint(Bc[ni].x), __float_as_uint(Bc[ni].y));
            #pragma unroll
            for (int ni = 0; ni < 6; ni++) Bc[ni] = Bn[ni];
        }

        float* og = out + (size_t)b * (NTOK * DIM);
        #pragma unroll
        for (int ni = 0; ni < 6; ni++) {
            int n = nc0 + ni * 8 + tg * 2;
            float2 pb = *(const float2*)&proj_b[n];
            if (rA < NTOK) *(float2*)&og[rA * DIM + n] =
                make_float2(acc[ni][0] + pb.x, acc[ni][1] + pb.y);
            if (rB < NTOK) *(float2*)&og[rB * DIM + n] =
                make_float2(acc[ni][2] + pb.x, acc[ni][3] + pb.y);
        }
    }
}

extern "C" void kernel_launch(void* const* d_in, const int* in_sizes, int n_in,
                              void* d_out, int out_size)
{
    const float* x          = (const float*)d_in[0];
    const float* qkv_w      = (const float*)d_in[2];
    const float* qkv_b      = (const float*)d_in[3];
    const float* proj_w     = (const float*)d_in[4];
    const float* proj_b     = (const float*)d_in[5];
    const float* bias_table = (const float*)d_in[6];
    const int*   rel_index  = (const int*)d_in[7];
    float* out = (float*)d_out;

    int nwin = in_sizes[0] / (NTOK * DIM);

    prep_kernel<<<54, 256>>>(qkv_w, proj_w, bias_table, rel_index);

    cudaFuncSetAttribute(win_attn_kernel,
                         cudaFuncAttributeMaxDynamicSharedMemorySize, SMEM_BYTES);
    win_attn_kernel<<<nwin, 288, SMEM_BYTES>>>(x, qkv_b, proj_b, out);
    (void)n_in; (void)out_size;
}